// round 13
// baseline (speedup 1.0000x reference)
#include <cuda_runtime.h>
#include <cuda_fp16.h>

#define NN 200000
#define NE 6400000
#define NG 1024
#define NEMB 1032
#define TPB 256
#define NREP 16
#define NBB ((NN + TPB - 1) / TPB)            // 782
#define NBB2 ((NN / 2 + TPB - 1) / TPB)       // 391 (2 nodes/thread)
#define NB_EDGE2 ((NE / 2 + TPB - 1) / TPB)   // 12500
#define NB_EDGE4 ((NE / 4 + TPB - 1) / TPB)   // 6250

struct __align__(32) H16 { uint4 a, b; };     // 16 packed halves, 32B-aligned

// Scratch (device globals; allocation-free)
__device__ H16    g_th[2][NN];           // layer-1 accumulators, f16 (32B/node)
__device__ H16    g_hsh[2][NN];          // hs1 packed f16 (gather source)
__device__ float2 g_rec[2][NN];          // {dis, batch bits}
__device__ uint4  g_wh[2][NN];           // w packed f16: 6 halves in 16B slot
__device__ uint4  g_t6[2][NN];           // layer-2 accumulators (preloaded w_i)
__device__ int    g_deg[2][NN];          // in-degree
__device__ float4 g_tab[NEMB * 4];       // emb @ W1 (66KB, L1/L2-hot)
__device__ float4 g_pool6[2 * NREP * NG * 2];  // [g][rep][graph][8 floats]
__device__ float  g_M[2][16][8];         // M_g = W2 @ P_g^T
__device__ float  g_b2P[2][8];           // b2 @ P_g^T

__device__ __forceinline__ unsigned h2u(__half2 h) { return *reinterpret_cast<unsigned*>(&h); }
__device__ __forceinline__ __half2 u2h(unsigned u) { return *reinterpret_cast<__half2*>(&u); }

__device__ __forceinline__ void red_add_v4(float* addr, float a, float b, float c, float d) {
    asm volatile("red.global.add.v4.f32 [%0], {%1,%2,%3,%4};"
                 :: "l"(addr), "f"(a), "f"(b), "f"(c), "f"(d) : "memory");
}
__device__ __forceinline__ void red_add_v2(float* addr, float a, float b) {
    asm volatile("red.global.add.v2.f32 [%0], {%1,%2};"
                 :: "l"(addr), "f"(a), "f"(b) : "memory");
}
__device__ __forceinline__ void red_add_v4h2(uint4* addr, uint4 v) {
    asm volatile("red.global.add.noftz.v4.f16x2 [%0], {%1,%2,%3,%4};"
                 :: "l"(addr), "r"(v.x), "r"(v.y), "r"(v.z), "r"(v.w) : "memory");
}
__device__ __forceinline__ void ldg256(const H16* p, uint4& a, uint4& b) {
    asm volatile("ld.global.nc.v8.b32 {%0,%1,%2,%3,%4,%5,%6,%7}, [%8];"
                 : "=r"(a.x), "=r"(a.y), "=r"(a.z), "=r"(a.w),
                   "=r"(b.x), "=r"(b.y), "=r"(b.z), "=r"(b.w)
                 : "l"(p));
}

// Prologue: zero deg/pool6 + tab = emb@W1 + projection mats
__global__ void k_init(const float* __restrict__ emb, const float* __restrict__ W1,
                       const float* __restrict__ W2, const float* __restrict__ b2,
                       const float* __restrict__ fcW) {
    int i = blockIdx.x * blockDim.x + threadIdx.x;
    if (i < NN) { g_deg[0][i] = 0; g_deg[1][i] = 0; }
    if (i < 2 * NREP * NG * 2) g_pool6[i] = make_float4(0.f, 0.f, 0.f, 0.f);
    if (blockIdx.x < (NEMB + TPB - 1) / TPB) {
        __shared__ float Ws[256];
        if (threadIdx.x < 256) Ws[threadIdx.x] = __ldg(W1 + threadIdx.x);
        __syncthreads();
        if (i < NEMB) {
            const float* x = emb + i * 16;
            float acc[16];
#pragma unroll
            for (int j = 0; j < 16; j++) acc[j] = 0.f;
#pragma unroll
            for (int k = 0; k < 16; k++) {
                float xk = __ldg(x + k);
#pragma unroll
                for (int j = 0; j < 16; j++) acc[j] += xk * Ws[k * 16 + j];
            }
            float4* o = g_tab + i * 4;
#pragma unroll
            for (int c = 0; c < 4; c++)
                o[c] = make_float4(acc[4*c], acc[4*c+1], acc[4*c+2], acc[4*c+3]);
        }
    }
    if (blockIdx.x == NBB - 1) {
        int t = threadIdx.x;
        if (t < 192) {
            int g = t / 96, r = t % 96, k = r / 6, o = r % 6;
            float s = 0.f;
#pragma unroll
            for (int j = 0; j < 16; j++) s += __ldg(W2 + k * 16 + j) * __ldg(fcW + o * 32 + 16 * g + j);
            g_M[g][k][o] = s;
        } else if (t < 204) {
            int g = (t - 192) / 6, o = (t - 192) % 6;
            float s = 0.f;
#pragma unroll
            for (int j = 0; j < 16; j++) s += __ldg(b2 + j) * __ldg(fcW + o * 32 + 16 * g + j);
            g_b2P[g][o] = s;
        }
    }
}

// In-degree count, both graphs, 4 edges/thread
__global__ void k_count(const int* __restrict__ ei0, const int* __restrict__ ei1) {
    int g = blockIdx.x >= NB_EDGE4 ? 1 : 0;
    const int* dst = (g ? ei1 : ei0) + NE;
    int i = (blockIdx.x - g * NB_EDGE4) * blockDim.x + threadIdx.x;
    int4 d = __ldg((const int4*)dst + i);
    int* deg = g_deg[g];
    atomicAdd(deg + d.x, 1);
    atomicAdd(deg + d.y, 1);
    atomicAdd(deg + d.z, 1);
    atomicAdd(deg + d.w, 1);
}

// 2 nodes/thread: dis; hs1 = tab[id]*dis -> f16 to g_hsh + g_th preload; rec (no cnt atomics)
__global__ void k_embed(const int* __restrict__ ids0, const int* __restrict__ ids1,
                        const int* __restrict__ b0, const int* __restrict__ b1) {
    int g = blockIdx.x >= NBB2 ? 1 : 0;
    int p = (blockIdx.x - g * NBB2) * blockDim.x + threadIdx.x;
    if (p >= NN / 2) return;
    int n0 = 2 * p;
    const int* ids = g ? ids1 : ids0;
    const int* bat = g ? b1 : b0;
    int2 dg = __ldg((const int2*)(g_deg[g]) + p);
    int2 id = __ldg((const int2*)ids + p);
    int2 bt = __ldg((const int2*)bat + p);
    float d0 = rsqrtf((float)dg.x + 1.0f);
    float d1 = rsqrtf((float)dg.y + 1.0f);
    float4 rr;
    rr.x = d0; rr.y = __int_as_float(bt.x);
    rr.z = d1; rr.w = __int_as_float(bt.y);
    *((float4*)(g_rec[g]) + p) = rr;
#pragma unroll
    for (int k = 0; k < 2; k++) {
        int n = n0 + k;
        float d = k ? d1 : d0;
        int idv = k ? id.y : id.x;
        const float4* tb = g_tab + (size_t)idv * 4;
        __half2 hh[8];
#pragma unroll
        for (int c = 0; c < 4; c++) {
            float4 v = __ldg(tb + c);
            hh[2*c]   = __float22half2_rn(make_float2(v.x * d, v.y * d));
            hh[2*c+1] = __float22half2_rn(make_float2(v.z * d, v.w * d));
        }
        uint4 a = make_uint4(h2u(hh[0]), h2u(hh[1]), h2u(hh[2]), h2u(hh[3]));
        uint4 b = make_uint4(h2u(hh[4]), h2u(hh[5]), h2u(hh[6]), h2u(hh[7]));
        g_hsh[g][n].a = a; g_hsh[g][n].b = b;
        g_th[g][n].a = a;  g_th[g][n].b = b;
    }
}

// Layer-1 edge pass: t[dst] += hs1[src], 2 edges/thread, 256-bit gathers
__global__ void k_edge1(const int* __restrict__ ei0, const int* __restrict__ ei1) {
    int g = blockIdx.x >= NB_EDGE2 ? 1 : 0;
    const int* ei = g ? ei1 : ei0;
    int i = (blockIdx.x - g * NB_EDGE2) * blockDim.x + threadIdx.x;
    int2 s = __ldg((const int2*)ei + i);
    int2 d = __ldg((const int2*)(ei + NE) + i);
    const H16* hs = g_hsh[g];
    H16* t = g_th[g];
    uint4 a0, b0, a1, b1;
    ldg256(hs + s.x, a0, b0);
    ldg256(hs + s.y, a1, b1);
    uint4* t0 = (uint4*)(t + d.x);
    uint4* t1 = (uint4*)(t + d.y);
    red_add_v4h2(t0, a0); red_add_v4h2(t0 + 1, b0);
    red_add_v4h2(t1, a1); red_add_v4h2(t1 + 1, b1);
}

// Layer-1 epilogue (1 node/thread): y = relu(d*t+b1); w = d*(y@M_g) -> wh + t6 preload
__global__ void k_post1(const float* __restrict__ b1p) {
    __shared__ float Ms[16][8];
    __shared__ float bs[16];
    int g = blockIdx.x >= NBB ? 1 : 0;
    if (threadIdx.x < 128) ((float*)Ms)[threadIdx.x] = ((const float*)g_M[g])[threadIdx.x];
    if (threadIdx.x >= 128 && threadIdx.x < 144) bs[threadIdx.x - 128] = __ldg(b1p + threadIdx.x - 128);
    __syncthreads();
    int i = (blockIdx.x - g * NBB) * blockDim.x + threadIdx.x;
    if (i >= NN) return;
    float d = g_rec[g][i].x;
    uint4 ta = g_th[g][i].a;
    uint4 tb = g_th[g][i].b;
    float y[16];
    {
        unsigned u[8] = {ta.x, ta.y, ta.z, ta.w, tb.x, tb.y, tb.z, tb.w};
#pragma unroll
        for (int c = 0; c < 8; c++) {
            float2 f = __half22float2(u2h(u[c]));
            y[2*c+0] = fmaxf(d * f.x + bs[2*c+0], 0.f);
            y[2*c+1] = fmaxf(d * f.y + bs[2*c+1], 0.f);
        }
    }
    float acc[6];
#pragma unroll
    for (int o = 0; o < 6; o++) acc[o] = 0.f;
#pragma unroll
    for (int k = 0; k < 16; k++) {
        float yk = y[k];
#pragma unroll
        for (int o = 0; o < 6; o++) acc[o] += yk * Ms[k][o];
    }
    __half2 p0 = __float22half2_rn(make_float2(d * acc[0], d * acc[1]));
    __half2 p1 = __float22half2_rn(make_float2(d * acc[2], d * acc[3]));
    __half2 p2 = __float22half2_rn(make_float2(d * acc[4], d * acc[5]));
    uint4 w = make_uint4(h2u(p0), h2u(p1), h2u(p2), 0u);
    g_wh[g][i] = w;
    g_t6[g][i] = w;
}

// Layer-2 edge pass: t6[dst] += w[src], 4 edges/thread
__global__ void k_edge2(const int* __restrict__ ei0, const int* __restrict__ ei1) {
    int g = blockIdx.x >= NB_EDGE4 ? 1 : 0;
    const int* ei = g ? ei1 : ei0;
    int i = (blockIdx.x - g * NB_EDGE4) * blockDim.x + threadIdx.x;
    int4 s = __ldg((const int4*)ei + i);
    int4 d = __ldg((const int4*)(ei + NE) + i);
    const uint4* w = g_wh[g];
    uint4* t6 = g_t6[g];
    uint4 w0 = __ldg(w + s.x);
    uint4 w1 = __ldg(w + s.y);
    uint4 w2 = __ldg(w + s.z);
    uint4 w3 = __ldg(w + s.w);
    red_add_v4h2(t6 + d.x, w0);
    red_add_v4h2(t6 + d.y, w1);
    red_add_v4h2(t6 + d.z, w2);
    red_add_v4h2(t6 + d.w, w3);
}

// Layer-2 epilogue (2 nodes/thread): pool6[batch] += dis*t6 + b2P,
// with warp-level aggregation exploiting SORTED batch ids.
__global__ void k_post2() {
    __shared__ float bps[8];
    int g = blockIdx.x >= NBB2 ? 1 : 0;
    if (threadIdx.x < 8) bps[threadIdx.x] = g_b2P[g][threadIdx.x];
    __syncthreads();
    int p = (blockIdx.x - g * NBB2) * blockDim.x + threadIdx.x;
    bool live = (p < NN / 2);
    int n0 = 2 * p;
    float4 rr = live ? *((const float4*)(g_rec[g]) + p) : make_float4(1.f, 0.f, 1.f, 0.f);
    int btA = __float_as_int(rr.y);
    int btB = __float_as_int(rr.w);
    float v[6];
#pragma unroll
    for (int o = 0; o < 6; o++) v[o] = 0.f;
    bool pairSame = (btA == btB);
    if (live) {
#pragma unroll
        for (int k = 0; k < 2; k++) {
            int n = n0 + k;
            float d = k ? rr.z : rr.x;
            uint4 t = g_t6[g][n];
            float2 f0 = __half22float2(u2h(t.x));
            float2 f1 = __half22float2(u2h(t.y));
            float2 f2 = __half22float2(u2h(t.z));
            float u[6] = { d*f0.x + bps[0], d*f0.y + bps[1], d*f1.x + bps[2],
                           d*f1.y + bps[3], d*f2.x + bps[4], d*f2.y + bps[5] };
            if (k == 0 || pairSame) {
#pragma unroll
                for (int o = 0; o < 6; o++) v[o] += u[o];
            } else {
                // second node in different graph: red it individually
                int rep = threadIdx.x & (NREP - 1);
                float* pp = (float*)&g_pool6[((size_t)(g * NREP + rep) * NG + btB) * 2];
                red_add_v4(pp, u[0], u[1], u[2], u[3]);
                red_add_v2(pp + 4, u[4], u[5]);
            }
        }
    }
    // warp-uniform graph check (batch sorted => contiguous)
    unsigned m = 0xffffffffu;
    int first = __shfl_sync(m, btA, 0);
    int last  = __shfl_sync(m, btB, 31);
    bool uniform = __all_sync(m, live) && (first == last);
    if (uniform) {
#pragma unroll
        for (int st = 1; st < 32; st <<= 1) {
#pragma unroll
            for (int o = 0; o < 6; o++) v[o] += __shfl_xor_sync(m, v[o], st);
        }
        if ((threadIdx.x & 31) == 0) {
            int rep = (threadIdx.x >> 5) & (NREP - 1);
            float* pp = (float*)&g_pool6[((size_t)(g * NREP + rep) * NG + btA) * 2];
            red_add_v4(pp, v[0], v[1], v[2], v[3]);
            red_add_v2(pp + 4, v[4], v[5]);
        }
    } else if (live) {
        int rep = threadIdx.x & (NREP - 1);
        float* pp = (float*)&g_pool6[((size_t)(g * NREP + rep) * NG + btA) * 2];
        red_add_v4(pp, v[0], v[1], v[2], v[3]);
        red_add_v2(pp + 4, v[4], v[5]);
    }
}

// Sum replicas; cnt via binary search on SORTED batch; /cnt; +fcb
__global__ void k_final(const float* __restrict__ fcb, float* __restrict__ out,
                        const int* __restrict__ b0, const int* __restrict__ b1) {
    int b = blockIdx.x * blockDim.x + threadIdx.x;
    if (b >= NG) return;
    float s[2][6];
    float cnt[2];
#pragma unroll
    for (int g = 0; g < 2; g++) {
#pragma unroll
        for (int o = 0; o < 6; o++) s[g][o] = 0.f;
        for (int rp = 0; rp < NREP; rp++) {
            const float4* pp = &g_pool6[((size_t)(g * NREP + rp) * NG + b) * 2];
            float4 a = pp[0];
            float4 c = pp[1];
            s[g][0] += a.x; s[g][1] += a.y; s[g][2] += a.z; s[g][3] += a.w;
            s[g][4] += c.x; s[g][5] += c.y;
        }
        const int* bat = g ? b1 : b0;
        // lower_bound(b) and lower_bound(b+1)
        int lo = 0, hi = NN;
        while (lo < hi) { int mid = (lo + hi) >> 1; if (__ldg(bat + mid) < b) lo = mid + 1; else hi = mid; }
        int lb = lo;
        lo = lb; hi = NN;
        while (lo < hi) { int mid = (lo + hi) >> 1; if (__ldg(bat + mid) < b + 1) lo = mid + 1; else hi = mid; }
        cnt[g] = (float)(lo - lb);
    }
    float inv_r = 1.0f / fmaxf(cnt[0], 1.0f);
    float inv_l = 1.0f / fmaxf(cnt[1], 1.0f);
#pragma unroll
    for (int o = 0; o < 6; o++) {
        float v = s[0][o] * inv_r + s[1][o] * inv_l + __ldg(fcb + o);
        if (o < 3) out[b * 3 + o] = v;
        else       out[NG * 3 + b * 3 + (o - 3)] = v;
    }
}

extern "C" void kernel_launch(void* const* d_in, const int* in_sizes, int n_in,
                              void* d_out, int out_size) {
    const float* emb = (const float*)d_in[0];
    const float* W1  = (const float*)d_in[1];
    const float* b1  = (const float*)d_in[2];
    const float* W2  = (const float*)d_in[3];
    const float* b2  = (const float*)d_in[4];
    const float* fcW = (const float*)d_in[5];
    const float* fcb = (const float*)d_in[6];
    const int* ids0  = (const int*)d_in[7];
    const int* ei0   = (const int*)d_in[8];
    const int* b0    = (const int*)d_in[9];
    const int* ids1  = (const int*)d_in[10];
    const int* ei1   = (const int*)d_in[11];
    const int* b1i   = (const int*)d_in[12];
    float* out = (float*)d_out;

    k_init <<<NBB, TPB>>>(emb, W1, W2, b2, fcW);
    k_count<<<2 * NB_EDGE4, TPB>>>(ei0, ei1);
    k_embed<<<2 * NBB2, TPB>>>(ids0, ids1, b0, b1i);
    k_edge1<<<2 * NB_EDGE2, TPB>>>(ei0, ei1);
    k_post1<<<2 * NBB, TPB>>>(b1);
    k_edge2<<<2 * NB_EDGE4, TPB>>>(ei0, ei1);
    k_post2<<<2 * NBB2, TPB>>>();
    k_final<<<(NG + TPB - 1) / TPB, TPB>>>(fcb, out, b0, b1i);
}

// round 14
// speedup vs baseline: 1.4652x; 1.4652x over previous
#include <cuda_runtime.h>
#include <cuda_fp16.h>

#define NN 200000
#define NE 6400000
#define NG 1024
#define NEMB 1032
#define TPB 256
#define NREP 16
#define NBB ((NN + TPB - 1) / TPB)            // 782
#define NBB2 ((NN / 2 + TPB - 1) / TPB)       // 391 (2 nodes/thread)
#define NB_EDGE2 ((NE / 2 + TPB - 1) / TPB)   // 12500
#define NB_EDGE4 ((NE / 4 + TPB - 1) / TPB)   // 6250

struct __align__(32) H16 { uint4 a, b; };     // 16 packed halves, 32B-aligned

// Scratch (device globals; allocation-free)
__device__ H16    g_th[2][NN];           // layer-1 accumulators, f16 (32B/node)
__device__ H16    g_hsh[2][NN];          // hs1 packed f16 (gather source)
__device__ float2 g_rec[2][NN];          // {dis, batch bits}
__device__ uint4  g_wh[2][NN];           // w packed f16: 6 halves in 16B slot
__device__ uint4  g_t6[2][NN];           // layer-2 accumulators (preloaded w_i)
__device__ int    g_deg[2][NN];          // in-degree
__device__ float4 g_tab[NEMB * 4];       // emb @ W1 (66KB, L1/L2-hot)
__device__ float4 g_pool6[2 * NREP * NG * 2];  // [g][rep][graph][8 floats]
__device__ float  g_M[2][16][8];         // M_g = W2 @ P_g^T
__device__ float  g_b2P[2][8];           // b2 @ P_g^T

__device__ __forceinline__ unsigned h2u(__half2 h) { return *reinterpret_cast<unsigned*>(&h); }
__device__ __forceinline__ __half2 u2h(unsigned u) { return *reinterpret_cast<__half2*>(&u); }

__device__ __forceinline__ void red_add_v4(float* addr, float a, float b, float c, float d) {
    asm volatile("red.global.add.v4.f32 [%0], {%1,%2,%3,%4};"
                 :: "l"(addr), "f"(a), "f"(b), "f"(c), "f"(d) : "memory");
}
__device__ __forceinline__ void red_add_v2(float* addr, float a, float b) {
    asm volatile("red.global.add.v2.f32 [%0], {%1,%2};"
                 :: "l"(addr), "f"(a), "f"(b) : "memory");
}
__device__ __forceinline__ void red_add_v4h2(uint4* addr, uint4 v) {
    asm volatile("red.global.add.noftz.v4.f16x2 [%0], {%1,%2,%3,%4};"
                 :: "l"(addr), "r"(v.x), "r"(v.y), "r"(v.z), "r"(v.w) : "memory");
}
__device__ __forceinline__ void ldg256(const H16* p, uint4& a, uint4& b) {
    asm volatile("ld.global.nc.v8.b32 {%0,%1,%2,%3,%4,%5,%6,%7}, [%8];"
                 : "=r"(a.x), "=r"(a.y), "=r"(a.z), "=r"(a.w),
                   "=r"(b.x), "=r"(b.y), "=r"(b.z), "=r"(b.w)
                 : "l"(p));
}

// Prologue: zero deg/pool6 + tab = emb@W1 + projection mats
__global__ void k_init(const float* __restrict__ emb, const float* __restrict__ W1,
                       const float* __restrict__ W2, const float* __restrict__ b2,
                       const float* __restrict__ fcW) {
    int i = blockIdx.x * blockDim.x + threadIdx.x;
    if (i < NN) { g_deg[0][i] = 0; g_deg[1][i] = 0; }
    if (i < 2 * NREP * NG * 2) g_pool6[i] = make_float4(0.f, 0.f, 0.f, 0.f);
    if (blockIdx.x < (NEMB + TPB - 1) / TPB) {
        __shared__ float Ws[256];
        if (threadIdx.x < 256) Ws[threadIdx.x] = __ldg(W1 + threadIdx.x);
        __syncthreads();
        if (i < NEMB) {
            const float* x = emb + i * 16;
            float acc[16];
#pragma unroll
            for (int j = 0; j < 16; j++) acc[j] = 0.f;
#pragma unroll
            for (int k = 0; k < 16; k++) {
                float xk = __ldg(x + k);
#pragma unroll
                for (int j = 0; j < 16; j++) acc[j] += xk * Ws[k * 16 + j];
            }
            float4* o = g_tab + i * 4;
#pragma unroll
            for (int c = 0; c < 4; c++)
                o[c] = make_float4(acc[4*c], acc[4*c+1], acc[4*c+2], acc[4*c+3]);
        }
    }
    if (blockIdx.x == NBB - 1) {
        int t = threadIdx.x;
        if (t < 192) {
            int g = t / 96, r = t % 96, k = r / 6, o = r % 6;
            float s = 0.f;
#pragma unroll
            for (int j = 0; j < 16; j++) s += __ldg(W2 + k * 16 + j) * __ldg(fcW + o * 32 + 16 * g + j);
            g_M[g][k][o] = s;
        } else if (t < 204) {
            int g = (t - 192) / 6, o = (t - 192) % 6;
            float s = 0.f;
#pragma unroll
            for (int j = 0; j < 16; j++) s += __ldg(b2 + j) * __ldg(fcW + o * 32 + 16 * g + j);
            g_b2P[g][o] = s;
        }
    }
}

// In-degree count, both graphs, 4 edges/thread
__global__ void k_count(const int* __restrict__ ei0, const int* __restrict__ ei1) {
    int g = blockIdx.x >= NB_EDGE4 ? 1 : 0;
    const int* dst = (g ? ei1 : ei0) + NE;
    int i = (blockIdx.x - g * NB_EDGE4) * blockDim.x + threadIdx.x;
    int4 d = __ldg((const int4*)dst + i);
    int* deg = g_deg[g];
    atomicAdd(deg + d.x, 1);
    atomicAdd(deg + d.y, 1);
    atomicAdd(deg + d.z, 1);
    atomicAdd(deg + d.w, 1);
}

// 2 nodes/thread: dis; hs1 = tab[id]*dis -> f16 to g_hsh + g_th preload; rec (no cnt atomics)
__global__ void k_embed(const int* __restrict__ ids0, const int* __restrict__ ids1,
                        const int* __restrict__ b0, const int* __restrict__ b1) {
    int g = blockIdx.x >= NBB2 ? 1 : 0;
    int p = (blockIdx.x - g * NBB2) * blockDim.x + threadIdx.x;
    if (p >= NN / 2) return;
    int n0 = 2 * p;
    const int* ids = g ? ids1 : ids0;
    const int* bat = g ? b1 : b0;
    int2 dg = __ldg((const int2*)(g_deg[g]) + p);
    int2 id = __ldg((const int2*)ids + p);
    int2 bt = __ldg((const int2*)bat + p);
    float d0 = rsqrtf((float)dg.x + 1.0f);
    float d1 = rsqrtf((float)dg.y + 1.0f);
    float4 rr;
    rr.x = d0; rr.y = __int_as_float(bt.x);
    rr.z = d1; rr.w = __int_as_float(bt.y);
    *((float4*)(g_rec[g]) + p) = rr;
#pragma unroll
    for (int k = 0; k < 2; k++) {
        int n = n0 + k;
        float d = k ? d1 : d0;
        int idv = k ? id.y : id.x;
        const float4* tb = g_tab + (size_t)idv * 4;
        __half2 hh[8];
#pragma unroll
        for (int c = 0; c < 4; c++) {
            float4 v = __ldg(tb + c);
            hh[2*c]   = __float22half2_rn(make_float2(v.x * d, v.y * d));
            hh[2*c+1] = __float22half2_rn(make_float2(v.z * d, v.w * d));
        }
        uint4 a = make_uint4(h2u(hh[0]), h2u(hh[1]), h2u(hh[2]), h2u(hh[3]));
        uint4 b = make_uint4(h2u(hh[4]), h2u(hh[5]), h2u(hh[6]), h2u(hh[7]));
        g_hsh[g][n].a = a; g_hsh[g][n].b = b;
        g_th[g][n].a = a;  g_th[g][n].b = b;
    }
}

// Layer-1 edge pass: t[dst] += hs1[src], 2 edges/thread, 256-bit gathers
__global__ void k_edge1(const int* __restrict__ ei0, const int* __restrict__ ei1) {
    int g = blockIdx.x >= NB_EDGE2 ? 1 : 0;
    const int* ei = g ? ei1 : ei0;
    int i = (blockIdx.x - g * NB_EDGE2) * blockDim.x + threadIdx.x;
    int2 s = __ldg((const int2*)ei + i);
    int2 d = __ldg((const int2*)(ei + NE) + i);
    const H16* hs = g_hsh[g];
    H16* t = g_th[g];
    uint4 a0, b0, a1, b1;
    ldg256(hs + s.x, a0, b0);
    ldg256(hs + s.y, a1, b1);
    uint4* t0 = (uint4*)(t + d.x);
    uint4* t1 = (uint4*)(t + d.y);
    red_add_v4h2(t0, a0); red_add_v4h2(t0 + 1, b0);
    red_add_v4h2(t1, a1); red_add_v4h2(t1 + 1, b1);
}

// Layer-1 epilogue (2 nodes/thread): y = relu(d*t+b1); w = d*(y@M_g) -> wh + t6 preload
__global__ void k_post1(const float* __restrict__ b1p) {
    __shared__ float Ms[16][8];
    __shared__ float bs[16];
    int g = blockIdx.x >= NBB2 ? 1 : 0;
    if (threadIdx.x < 128) ((float*)Ms)[threadIdx.x] = ((const float*)g_M[g])[threadIdx.x];
    if (threadIdx.x >= 128 && threadIdx.x < 144) bs[threadIdx.x - 128] = __ldg(b1p + threadIdx.x - 128);
    __syncthreads();
    int p = (blockIdx.x - g * NBB2) * blockDim.x + threadIdx.x;
    if (p >= NN / 2) return;
    int n0 = 2 * p;
    float4 rr = *((const float4*)(g_rec[g]) + p);
#pragma unroll
    for (int k = 0; k < 2; k++) {
        int n = n0 + k;
        float d = k ? rr.z : rr.x;
        uint4 ta = g_th[g][n].a;
        uint4 tb = g_th[g][n].b;
        float y[16];
        {
            unsigned u[8] = {ta.x, ta.y, ta.z, ta.w, tb.x, tb.y, tb.z, tb.w};
#pragma unroll
            for (int c = 0; c < 8; c++) {
                float2 f = __half22float2(u2h(u[c]));
                y[2*c+0] = fmaxf(d * f.x + bs[2*c+0], 0.f);
                y[2*c+1] = fmaxf(d * f.y + bs[2*c+1], 0.f);
            }
        }
        float acc[6];
#pragma unroll
        for (int o = 0; o < 6; o++) acc[o] = 0.f;
#pragma unroll
        for (int kk = 0; kk < 16; kk++) {
            float yk = y[kk];
#pragma unroll
            for (int o = 0; o < 6; o++) acc[o] += yk * Ms[kk][o];
        }
        __half2 p0 = __float22half2_rn(make_float2(d * acc[0], d * acc[1]));
        __half2 p1 = __float22half2_rn(make_float2(d * acc[2], d * acc[3]));
        __half2 p2 = __float22half2_rn(make_float2(d * acc[4], d * acc[5]));
        uint4 w = make_uint4(h2u(p0), h2u(p1), h2u(p2), 0u);
        g_wh[g][n] = w;
        g_t6[g][n] = w;
    }
}

// Layer-2 edge pass: t6[dst] += w[src], 4 edges/thread
__global__ void k_edge2(const int* __restrict__ ei0, const int* __restrict__ ei1) {
    int g = blockIdx.x >= NB_EDGE4 ? 1 : 0;
    const int* ei = g ? ei1 : ei0;
    int i = (blockIdx.x - g * NB_EDGE4) * blockDim.x + threadIdx.x;
    int4 s = __ldg((const int4*)ei + i);
    int4 d = __ldg((const int4*)(ei + NE) + i);
    const uint4* w = g_wh[g];
    uint4* t6 = g_t6[g];
    uint4 w0 = __ldg(w + s.x);
    uint4 w1 = __ldg(w + s.y);
    uint4 w2 = __ldg(w + s.z);
    uint4 w3 = __ldg(w + s.w);
    red_add_v4h2(t6 + d.x, w0);
    red_add_v4h2(t6 + d.y, w1);
    red_add_v4h2(t6 + d.z, w2);
    red_add_v4h2(t6 + d.w, w3);
}

// Layer-2 epilogue (2 nodes/thread): pool6[batch] += dis*t6 + b2P
__global__ void k_post2() {
    __shared__ float bps[8];
    int g = blockIdx.x >= NBB2 ? 1 : 0;
    if (threadIdx.x < 8) bps[threadIdx.x] = g_b2P[g][threadIdx.x];
    __syncthreads();
    int p = (blockIdx.x - g * NBB2) * blockDim.x + threadIdx.x;
    if (p >= NN / 2) return;
    int n0 = 2 * p;
    float4 rr = *((const float4*)(g_rec[g]) + p);
    int rep = threadIdx.x & (NREP - 1);
#pragma unroll
    for (int k = 0; k < 2; k++) {
        int n = n0 + k;
        float d = k ? rr.z : rr.x;
        int bt = __float_as_int(k ? rr.w : rr.y);
        uint4 t = g_t6[g][n];
        float2 f0 = __half22float2(u2h(t.x));
        float2 f1 = __half22float2(u2h(t.y));
        float2 f2 = __half22float2(u2h(t.z));
        float* pp = (float*)&g_pool6[((size_t)(g * NREP + rep) * NG + bt) * 2];
        red_add_v4(pp, d * f0.x + bps[0], d * f0.y + bps[1], d * f1.x + bps[2], d * f1.y + bps[3]);
        red_add_v2(pp + 4, d * f2.x + bps[4], d * f2.y + bps[5]);
    }
}

// Sum replicas; cnt via binary search on SORTED batch; /cnt; +fcb
__global__ void k_final(const float* __restrict__ fcb, float* __restrict__ out,
                        const int* __restrict__ b0, const int* __restrict__ b1) {
    int b = blockIdx.x * blockDim.x + threadIdx.x;
    if (b >= NG) return;
    float s[2][6];
    float cnt[2];
#pragma unroll
    for (int g = 0; g < 2; g++) {
#pragma unroll
        for (int o = 0; o < 6; o++) s[g][o] = 0.f;
        for (int rp = 0; rp < NREP; rp++) {
            const float4* pp = &g_pool6[((size_t)(g * NREP + rp) * NG + b) * 2];
            float4 a = pp[0];
            float4 c = pp[1];
            s[g][0] += a.x; s[g][1] += a.y; s[g][2] += a.z; s[g][3] += a.w;
            s[g][4] += c.x; s[g][5] += c.y;
        }
        const int* bat = g ? b1 : b0;
        int lo = 0, hi = NN;
        while (lo < hi) { int mid = (lo + hi) >> 1; if (__ldg(bat + mid) < b) lo = mid + 1; else hi = mid; }
        int lb = lo;
        lo = lb; hi = NN;
        while (lo < hi) { int mid = (lo + hi) >> 1; if (__ldg(bat + mid) < b + 1) lo = mid + 1; else hi = mid; }
        cnt[g] = (float)(lo - lb);
    }
    float inv_r = 1.0f / fmaxf(cnt[0], 1.0f);
    float inv_l = 1.0f / fmaxf(cnt[1], 1.0f);
#pragma unroll
    for (int o = 0; o < 6; o++) {
        float v = s[0][o] * inv_r + s[1][o] * inv_l + __ldg(fcb + o);
        if (o < 3) out[b * 3 + o] = v;
        else       out[NG * 3 + b * 3 + (o - 3)] = v;
    }
}

extern "C" void kernel_launch(void* const* d_in, const int* in_sizes, int n_in,
                              void* d_out, int out_size) {
    const float* emb = (const float*)d_in[0];
    const float* W1  = (const float*)d_in[1];
    const float* b1  = (const float*)d_in[2];
    const float* W2  = (const float*)d_in[3];
    const float* b2  = (const float*)d_in[4];
    const float* fcW = (const float*)d_in[5];
    const float* fcb = (const float*)d_in[6];
    const int* ids0  = (const int*)d_in[7];
    const int* ei0   = (const int*)d_in[8];
    const int* b0    = (const int*)d_in[9];
    const int* ids1  = (const int*)d_in[10];
    const int* ei1   = (const int*)d_in[11];
    const int* b1i   = (const int*)d_in[12];
    float* out = (float*)d_out;

    k_init <<<NBB, TPB>>>(emb, W1, W2, b2, fcW);
    k_count<<<2 * NB_EDGE4, TPB>>>(ei0, ei1);
    k_embed<<<2 * NBB2, TPB>>>(ids0, ids1, b0, b1i);
    k_edge1<<<2 * NB_EDGE2, TPB>>>(ei0, ei1);
    k_post1<<<2 * NBB2, TPB>>>(b1);
    k_edge2<<<2 * NB_EDGE4, TPB>>>(ei0, ei1);
    k_post2<<<2 * NBB2, TPB>>>();
    k_final<<<(NG + TPB - 1) / TPB, TPB>>>(fcb, out, b0, b1i);
}

// round 15
// speedup vs baseline: 1.5168x; 1.0352x over previous
#include <cuda_runtime.h>
#include <cuda_fp16.h>

#define NN 200000
#define NE 6400000
#define NG 1024
#define NEMB 1032
#define TPB 256
#define NREP 16
#define NBB ((NN + TPB - 1) / TPB)            // 782
#define NBB2 ((NN / 2 + TPB - 1) / TPB)       // 391 (2 nodes/thread)
#define NB_EDGE2 ((NE / 2 + TPB - 1) / TPB)   // 12500
#define NB_EDGE4 ((NE / 4 + TPB - 1) / TPB)   // 6250

struct __align__(32) H16 { uint4 a, b; };     // 16 packed halves, 32B-aligned

// Scratch (device globals; allocation-free)
__device__ H16    g_th[2][NN];           // layer-1 accumulators, f16 (32B/node)
__device__ H16    g_hsh[2][NN];          // hs1 packed f16 (gather source)
__device__ float2 g_rec[2][NN];          // {dis, batch bits}
__device__ uint4  g_wh[2][NN];           // w packed f16: 6 halves in 16B slot
__device__ uint4  g_t6[2][NN];           // layer-2 accumulators (preloaded w_i)
__device__ int    g_deg[2][NN];          // in-degree
__device__ float4 g_tab[NEMB * 4];       // emb @ W1 (66KB, L1/L2-hot)
__device__ float4 g_pool6[2 * NREP * NG * 2];  // [g][rep][graph][8 floats]
__device__ float  g_M[2][16][8];         // M_g = W2 @ P_g^T
__device__ float  g_b2P[2][8];           // b2 @ P_g^T

__device__ __forceinline__ unsigned h2u(__half2 h) { return *reinterpret_cast<unsigned*>(&h); }
__device__ __forceinline__ __half2 u2h(unsigned u) { return *reinterpret_cast<__half2*>(&u); }

__device__ __forceinline__ void red_add_v4(float* addr, float a, float b, float c, float d) {
    asm volatile("red.global.add.v4.f32 [%0], {%1,%2,%3,%4};"
                 :: "l"(addr), "f"(a), "f"(b), "f"(c), "f"(d) : "memory");
}
__device__ __forceinline__ void red_add_v2(float* addr, float a, float b) {
    asm volatile("red.global.add.v2.f32 [%0], {%1,%2};"
                 :: "l"(addr), "f"(a), "f"(b) : "memory");
}
__device__ __forceinline__ void red_add_v4h2(uint4* addr, uint4 v) {
    asm volatile("red.global.add.noftz.v4.f16x2 [%0], {%1,%2,%3,%4};"
                 :: "l"(addr), "r"(v.x), "r"(v.y), "r"(v.z), "r"(v.w) : "memory");
}
__device__ __forceinline__ void ldg256(const H16* p, uint4& a, uint4& b) {
    asm volatile("ld.global.nc.v8.b32 {%0,%1,%2,%3,%4,%5,%6,%7}, [%8];"
                 : "=r"(a.x), "=r"(a.y), "=r"(a.z), "=r"(a.w),
                   "=r"(b.x), "=r"(b.y), "=r"(b.z), "=r"(b.w)
                 : "l"(p));
}

// Prologue: zero deg/pool6 + tab = emb@W1 + projection mats (both graphs)
__global__ void k_init(const float* __restrict__ emb, const float* __restrict__ W1,
                       const float* __restrict__ W2, const float* __restrict__ b2,
                       const float* __restrict__ fcW) {
    int i = blockIdx.x * blockDim.x + threadIdx.x;
    if (i < NN) { g_deg[0][i] = 0; g_deg[1][i] = 0; }
    if (i < 2 * NREP * NG * 2) g_pool6[i] = make_float4(0.f, 0.f, 0.f, 0.f);
    if (blockIdx.x < (NEMB + TPB - 1) / TPB) {
        __shared__ float Ws[256];
        if (threadIdx.x < 256) Ws[threadIdx.x] = __ldg(W1 + threadIdx.x);
        __syncthreads();
        if (i < NEMB) {
            const float* x = emb + i * 16;
            float acc[16];
#pragma unroll
            for (int j = 0; j < 16; j++) acc[j] = 0.f;
#pragma unroll
            for (int k = 0; k < 16; k++) {
                float xk = __ldg(x + k);
#pragma unroll
                for (int j = 0; j < 16; j++) acc[j] += xk * Ws[k * 16 + j];
            }
            float4* o = g_tab + i * 4;
#pragma unroll
            for (int c = 0; c < 4; c++)
                o[c] = make_float4(acc[4*c], acc[4*c+1], acc[4*c+2], acc[4*c+3]);
        }
    }
    if (blockIdx.x == NBB - 1) {
        int t = threadIdx.x;
        if (t < 192) {
            int g = t / 96, r = t % 96, k = r / 6, o = r % 6;
            float s = 0.f;
#pragma unroll
            for (int j = 0; j < 16; j++) s += __ldg(W2 + k * 16 + j) * __ldg(fcW + o * 32 + 16 * g + j);
            g_M[g][k][o] = s;
        } else if (t < 204) {
            int g = (t - 192) / 6, o = (t - 192) % 6;
            float s = 0.f;
#pragma unroll
            for (int j = 0; j < 16; j++) s += __ldg(b2 + j) * __ldg(fcW + o * 32 + 16 * g + j);
            g_b2P[g][o] = s;
        }
    }
}

// Per-graph kernels (graph selected by arg g)

__global__ void k_count(const int* __restrict__ ei, int g) {
    int i = blockIdx.x * blockDim.x + threadIdx.x;
    int4 d = __ldg((const int4*)(ei + NE) + i);
    int* deg = g_deg[g];
    atomicAdd(deg + d.x, 1);
    atomicAdd(deg + d.y, 1);
    atomicAdd(deg + d.z, 1);
    atomicAdd(deg + d.w, 1);
}

__global__ void k_embed(const int* __restrict__ ids, const int* __restrict__ bat, int g) {
    int p = blockIdx.x * blockDim.x + threadIdx.x;
    if (p >= NN / 2) return;
    int n0 = 2 * p;
    int2 dg = __ldg((const int2*)(g_deg[g]) + p);
    int2 id = __ldg((const int2*)ids + p);
    int2 bt = __ldg((const int2*)bat + p);
    float d0 = rsqrtf((float)dg.x + 1.0f);
    float d1 = rsqrtf((float)dg.y + 1.0f);
    float4 rr;
    rr.x = d0; rr.y = __int_as_float(bt.x);
    rr.z = d1; rr.w = __int_as_float(bt.y);
    *((float4*)(g_rec[g]) + p) = rr;
#pragma unroll
    for (int k = 0; k < 2; k++) {
        int n = n0 + k;
        float d = k ? d1 : d0;
        int idv = k ? id.y : id.x;
        const float4* tb = g_tab + (size_t)idv * 4;
        __half2 hh[8];
#pragma unroll
        for (int c = 0; c < 4; c++) {
            float4 v = __ldg(tb + c);
            hh[2*c]   = __float22half2_rn(make_float2(v.x * d, v.y * d));
            hh[2*c+1] = __float22half2_rn(make_float2(v.z * d, v.w * d));
        }
        uint4 a = make_uint4(h2u(hh[0]), h2u(hh[1]), h2u(hh[2]), h2u(hh[3]));
        uint4 b = make_uint4(h2u(hh[4]), h2u(hh[5]), h2u(hh[6]), h2u(hh[7]));
        g_hsh[g][n].a = a; g_hsh[g][n].b = b;
        g_th[g][n].a = a;  g_th[g][n].b = b;
    }
}

__global__ void k_edge1(const int* __restrict__ ei, int g) {
    int i = blockIdx.x * blockDim.x + threadIdx.x;
    int2 s = __ldg((const int2*)ei + i);
    int2 d = __ldg((const int2*)(ei + NE) + i);
    const H16* hs = g_hsh[g];
    H16* t = g_th[g];
    uint4 a0, b0, a1, b1;
    ldg256(hs + s.x, a0, b0);
    ldg256(hs + s.y, a1, b1);
    uint4* t0 = (uint4*)(t + d.x);
    uint4* t1 = (uint4*)(t + d.y);
    red_add_v4h2(t0, a0); red_add_v4h2(t0 + 1, b0);
    red_add_v4h2(t1, a1); red_add_v4h2(t1 + 1, b1);
}

__global__ void k_post1(const float* __restrict__ b1p, int g) {
    __shared__ float Ms[16][8];
    __shared__ float bs[16];
    if (threadIdx.x < 128) ((float*)Ms)[threadIdx.x] = ((const float*)g_M[g])[threadIdx.x];
    if (threadIdx.x >= 128 && threadIdx.x < 144) bs[threadIdx.x - 128] = __ldg(b1p + threadIdx.x - 128);
    __syncthreads();
    int p = blockIdx.x * blockDim.x + threadIdx.x;
    if (p >= NN / 2) return;
    int n0 = 2 * p;
    float4 rr = *((const float4*)(g_rec[g]) + p);
#pragma unroll
    for (int k = 0; k < 2; k++) {
        int n = n0 + k;
        float d = k ? rr.z : rr.x;
        uint4 ta = g_th[g][n].a;
        uint4 tb = g_th[g][n].b;
        float y[16];
        {
            unsigned u[8] = {ta.x, ta.y, ta.z, ta.w, tb.x, tb.y, tb.z, tb.w};
#pragma unroll
            for (int c = 0; c < 8; c++) {
                float2 f = __half22float2(u2h(u[c]));
                y[2*c+0] = fmaxf(d * f.x + bs[2*c+0], 0.f);
                y[2*c+1] = fmaxf(d * f.y + bs[2*c+1], 0.f);
            }
        }
        float acc[6];
#pragma unroll
        for (int o = 0; o < 6; o++) acc[o] = 0.f;
#pragma unroll
        for (int kk = 0; kk < 16; kk++) {
            float yk = y[kk];
#pragma unroll
            for (int o = 0; o < 6; o++) acc[o] += yk * Ms[kk][o];
        }
        __half2 p0 = __float22half2_rn(make_float2(d * acc[0], d * acc[1]));
        __half2 p1 = __float22half2_rn(make_float2(d * acc[2], d * acc[3]));
        __half2 p2 = __float22half2_rn(make_float2(d * acc[4], d * acc[5]));
        uint4 w = make_uint4(h2u(p0), h2u(p1), h2u(p2), 0u);
        g_wh[g][n] = w;
        g_t6[g][n] = w;
    }
}

__global__ void k_edge2(const int* __restrict__ ei, int g) {
    int i = blockIdx.x * blockDim.x + threadIdx.x;
    int4 s = __ldg((const int4*)ei + i);
    int4 d = __ldg((const int4*)(ei + NE) + i);
    const uint4* w = g_wh[g];
    uint4* t6 = g_t6[g];
    uint4 w0 = __ldg(w + s.x);
    uint4 w1 = __ldg(w + s.y);
    uint4 w2 = __ldg(w + s.z);
    uint4 w3 = __ldg(w + s.w);
    red_add_v4h2(t6 + d.x, w0);
    red_add_v4h2(t6 + d.y, w1);
    red_add_v4h2(t6 + d.z, w2);
    red_add_v4h2(t6 + d.w, w3);
}

__global__ void k_post2(int g) {
    __shared__ float bps[8];
    if (threadIdx.x < 8) bps[threadIdx.x] = g_b2P[g][threadIdx.x];
    __syncthreads();
    int p = blockIdx.x * blockDim.x + threadIdx.x;
    if (p >= NN / 2) return;
    int n0 = 2 * p;
    float4 rr = *((const float4*)(g_rec[g]) + p);
    int rep = threadIdx.x & (NREP - 1);
#pragma unroll
    for (int k = 0; k < 2; k++) {
        int n = n0 + k;
        float d = k ? rr.z : rr.x;
        int bt = __float_as_int(k ? rr.w : rr.y);
        uint4 t = g_t6[g][n];
        float2 f0 = __half22float2(u2h(t.x));
        float2 f1 = __half22float2(u2h(t.y));
        float2 f2 = __half22float2(u2h(t.z));
        float* pp = (float*)&g_pool6[((size_t)(g * NREP + rep) * NG + bt) * 2];
        red_add_v4(pp, d * f0.x + bps[0], d * f0.y + bps[1], d * f1.x + bps[2], d * f1.y + bps[3]);
        red_add_v2(pp + 4, d * f2.x + bps[4], d * f2.y + bps[5]);
    }
}

// Sum replicas; cnt via binary search on SORTED batch; /cnt; +fcb
__global__ void k_final(const float* __restrict__ fcb, float* __restrict__ out,
                        const int* __restrict__ b0, const int* __restrict__ b1) {
    int b = blockIdx.x * blockDim.x + threadIdx.x;
    if (b >= NG) return;
    float s[2][6];
    float cnt[2];
#pragma unroll
    for (int g = 0; g < 2; g++) {
#pragma unroll
        for (int o = 0; o < 6; o++) s[g][o] = 0.f;
        for (int rp = 0; rp < NREP; rp++) {
            const float4* pp = &g_pool6[((size_t)(g * NREP + rp) * NG + b) * 2];
            float4 a = pp[0];
            float4 c = pp[1];
            s[g][0] += a.x; s[g][1] += a.y; s[g][2] += a.z; s[g][3] += a.w;
            s[g][4] += c.x; s[g][5] += c.y;
        }
        const int* bat = g ? b1 : b0;
        int lo = 0, hi = NN;
        while (lo < hi) { int mid = (lo + hi) >> 1; if (__ldg(bat + mid) < b) lo = mid + 1; else hi = mid; }
        int lb = lo;
        lo = lb; hi = NN;
        while (lo < hi) { int mid = (lo + hi) >> 1; if (__ldg(bat + mid) < b + 1) lo = mid + 1; else hi = mid; }
        cnt[g] = (float)(lo - lb);
    }
    float inv_r = 1.0f / fmaxf(cnt[0], 1.0f);
    float inv_l = 1.0f / fmaxf(cnt[1], 1.0f);
#pragma unroll
    for (int o = 0; o < 6; o++) {
        float v = s[0][o] * inv_r + s[1][o] * inv_l + __ldg(fcb + o);
        if (o < 3) out[b * 3 + o] = v;
        else       out[NG * 3 + b * 3 + (o - 3)] = v;
    }
}

extern "C" void kernel_launch(void* const* d_in, const int* in_sizes, int n_in,
                              void* d_out, int out_size) {
    const float* emb = (const float*)d_in[0];
    const float* W1  = (const float*)d_in[1];
    const float* b1  = (const float*)d_in[2];
    const float* W2  = (const float*)d_in[3];
    const float* b2  = (const float*)d_in[4];
    const float* fcW = (const float*)d_in[5];
    const float* fcb = (const float*)d_in[6];
    const int* ids0  = (const int*)d_in[7];
    const int* ei0   = (const int*)d_in[8];
    const int* b0    = (const int*)d_in[9];
    const int* ids1  = (const int*)d_in[10];
    const int* ei1   = (const int*)d_in[11];
    const int* b1i   = (const int*)d_in[12];
    float* out = (float*)d_out;

    const int* ids_g[2] = { ids0, ids1 };
    const int* ei_g[2]  = { ei0,  ei1  };

    // Fork a side stream for graph 1 (capture-legal event fork/join).
    cudaStream_t s1;
    cudaStreamCreateWithFlags(&s1, cudaStreamNonBlocking);
    cudaEvent_t eFork, eJoin;
    cudaEventCreateWithFlags(&eFork, cudaEventDisableTiming);
    cudaEventCreateWithFlags(&eJoin, cudaEventDisableTiming);

    k_init<<<NBB, TPB>>>(emb, W1, W2, b2, fcW);
    cudaEventRecord(eFork, 0);
    cudaStreamWaitEvent(s1, eFork, 0);

    for (int g = 0; g < 2; g++) {
        cudaStream_t st = g ? s1 : (cudaStream_t)0;
        k_count<<<NB_EDGE4, TPB, 0, st>>>(ei_g[g], g);
        k_embed<<<NBB2, TPB, 0, st>>>(ids_g[g], g ? b1i : b0, g);
        k_edge1<<<NB_EDGE2, TPB, 0, st>>>(ei_g[g], g);
        k_post1<<<NBB2, TPB, 0, st>>>(b1, g);
        k_edge2<<<NB_EDGE4, TPB, 0, st>>>(ei_g[g], g);
        k_post2<<<NBB2, TPB, 0, st>>>(g);
    }

    cudaEventRecord(eJoin, s1);
    cudaStreamWaitEvent((cudaStream_t)0, eJoin, 0);
    k_final<<<(NG + TPB - 1) / TPB, TPB>>>(fcb, out, b0, b1i);

    cudaEventDestroy(eFork);
    cudaEventDestroy(eJoin);
    cudaStreamDestroy(s1);
}